// round 7
// baseline (speedup 1.0000x reference)
#include <cuda_runtime.h>
#include <cuda_fp16.h>
#include <cstdint>

#define NE 16
#define DIN 128
#define HID 512
#define DOUT 64
#define BATCH 8192

// ---------------- device scratch (16B aligned for cp.async) ----------------
__device__ __align__(16) __half g_W1h[NE * HID * DIN];
__device__ __align__(16) __half g_W1l[NE * HID * DIN];
__device__ __align__(16) __half g_W2h[NE * HID * HID];
__device__ __align__(16) __half g_W2l[NE * HID * HID];
__device__ __align__(16) __half g_W3h[NE * DOUT * HID];
__device__ __align__(16) __half g_W3l[NE * DOUT * HID];
__device__ float g_part[(size_t)NE * BATCH * DOUT];

// ---------------- smem map (bytes) ----------------
// X / h2 region: 64 rows x 136 halves (272B stride) hi + lo
#define SM_XH   0
#define SM_XL   17408
// 3 weight buffers: each 64 rows x 72 halves (144B) hi (9216) + lo (9216)
#define SM_BUF  34816
#define BUF_SZ  18432
// h1: 64 rows x 520 halves (1040B stride) hi + lo
#define SM_H1H  90112
#define SM_H1L  156672
#define SM_B1   223232
#define SM_B2   225280
#define SM_B3   227328
#define SMEM_SZ 227584

__device__ __forceinline__ uint32_t smem_u32(const void* p) {
    uint32_t a;
    asm("{ .reg .u64 t; cvta.to.shared.u64 t, %1; cvt.u32.u64 %0, t; }" : "=r"(a) : "l"(p));
    return a;
}
#define CP_COMMIT asm volatile("cp.async.commit_group;" ::: "memory")
#define CP_WAIT1  asm volatile("cp.async.wait_group 1;" ::: "memory")

__device__ __forceinline__ void mma16816(float* c, uint32_t a0, uint32_t a1, uint32_t a2,
                                         uint32_t a3, uint32_t b0, uint32_t b1) {
    asm volatile(
        "mma.sync.aligned.m16n8k16.row.col.f32.f16.f16.f32 "
        "{%0,%1,%2,%3},{%4,%5,%6,%7},{%8,%9},{%0,%1,%2,%3};"
        : "+f"(c[0]), "+f"(c[1]), "+f"(c[2]), "+f"(c[3])
        : "r"(a0), "r"(a1), "r"(a2), "r"(a3), "r"(b0), "r"(b1));
}

// ---------------- panel source schedule ----------------
struct Src { const __half* h; const __half* l; int stride; };

__device__ __forceinline__ Src panel_src(int e, int P) {
    Src s;
    if (P < 16) {
        int nc = P >> 1, hf = P & 1;
        size_t o = ((size_t)e * HID + nc * 64) * DIN + hf * 64;
        s.h = g_W1h + o; s.l = g_W1l + o; s.stride = DIN;
        return s;
    }
    int Q = P - 16, nc = Q / 9, j = Q - nc * 9;
    if (j < 8) {
        size_t o = ((size_t)e * HID + nc * 64) * HID + j * 64;
        s.h = g_W2h + o; s.l = g_W2l + o; s.stride = HID;
        return s;
    }
    size_t o = (size_t)e * DOUT * HID + nc * 64;
    s.h = g_W3h + o; s.l = g_W3l + o; s.stride = HID;
    return s;
}

// load one weight panel [64n x 64k] hi+lo into a buffer (row stride 144 B)
__device__ __forceinline__ void load_panel(uint32_t sb, uint32_t buf, Src s, int tid) {
#pragma unroll
    for (int i = 0; i < 4; i++) {
        int idx = tid + i * 128;                 // 0..511
        int r = idx >> 3, j = idx & 7;
        uint32_t d = sb + buf + r * 144 + j * 16;
        const __half* pH = s.h + (size_t)r * s.stride + j * 8;
        const __half* pL = s.l + (size_t)r * s.stride + j * 8;
        asm volatile("cp.async.cg.shared.global [%0], [%1], 16;" :: "r"(d), "l"(pH));
        asm volatile("cp.async.cg.shared.global [%0], [%1], 16;" :: "r"(d + 9216), "l"(pL));
    }
}

// one K=64 panel, warp tile 32m x 32n, 3-term: Ah*Wh + Al*Wh + Ah*Wl
__device__ __forceinline__ void gemm32(const char* sm, uint32_t aH, uint32_t aLd,
                                       uint32_t astr, uint32_t wb, float* acc) {
#pragma unroll
    for (int k16 = 0; k16 < 4; k16++) {
        uint32_t ah[8], al[8];
#pragma unroll
        for (int mb = 0; mb < 2; mb++) {
            uint32_t o = aH + mb * 16 * astr + k16 * 32;
            ah[mb * 4 + 0] = *(const uint32_t*)(sm + o);
            ah[mb * 4 + 1] = *(const uint32_t*)(sm + o + astr * 8);
            ah[mb * 4 + 2] = *(const uint32_t*)(sm + o + 16);
            ah[mb * 4 + 3] = *(const uint32_t*)(sm + o + astr * 8 + 16);
            al[mb * 4 + 0] = *(const uint32_t*)(sm + o + aLd);
            al[mb * 4 + 1] = *(const uint32_t*)(sm + o + aLd + astr * 8);
            al[mb * 4 + 2] = *(const uint32_t*)(sm + o + aLd + 16);
            al[mb * 4 + 3] = *(const uint32_t*)(sm + o + aLd + astr * 8 + 16);
        }
#pragma unroll
        for (int nb = 0; nb < 4; nb++) {
            uint32_t bo = wb + nb * (8 * 144) + k16 * 32;
            uint32_t b0 = *(const uint32_t*)(sm + bo);
            uint32_t b1 = *(const uint32_t*)(sm + bo + 16);
            uint32_t w0 = *(const uint32_t*)(sm + bo + 9216);
            uint32_t w1 = *(const uint32_t*)(sm + bo + 9216 + 16);
#pragma unroll
            for (int mb = 0; mb < 2; mb++) {
                float* c = acc + (mb * 4 + nb) * 4;
                mma16816(c, ah[mb*4], ah[mb*4+1], ah[mb*4+2], ah[mb*4+3], b0, b1);
                mma16816(c, al[mb*4], al[mb*4+1], al[mb*4+2], al[mb*4+3], b0, b1);
                mma16816(c, ah[mb*4], ah[mb*4+1], ah[mb*4+2], ah[mb*4+3], w0, w1);
            }
        }
    }
}

__device__ __forceinline__ void split_st(char* sm, uint32_t oh, int lod, float v0, float v1) {
    __half h0 = __float2half_rn(v0), h1 = __float2half_rn(v1);
    __half l0 = __float2half_rn(v0 - __half2float(h0));
    __half l1 = __float2half_rn(v1 - __half2float(h1));
    *(__half2*)(sm + oh) = __halves2half2(h0, h1);
    *(__half2*)(sm + oh + lod) = __halves2half2(l0, l1);
}

// relu(acc+bias) -> hi/lo fp16 tile store (warp tile 32x32)
__device__ __forceinline__ void epi32(char* sm, uint32_t dstH, int lod, int strB,
                                      const float* bias, const float* acc,
                                      int mrow, int ncol) {
#pragma unroll
    for (int mb = 0; mb < 2; mb++)
#pragma unroll
        for (int nb = 0; nb < 4; nb++) {
            const float* c = acc + (mb * 4 + nb) * 4;
            int cc = ncol + nb * 8;
            int r = mrow + mb * 16;
            float v00 = fmaxf(c[0] + bias[cc], 0.f);
            float v01 = fmaxf(c[1] + bias[cc + 1], 0.f);
            float v10 = fmaxf(c[2] + bias[cc], 0.f);
            float v11 = fmaxf(c[3] + bias[cc + 1], 0.f);
            split_st(sm, dstH + r * strB + cc * 2, lod, v00, v01);
            split_st(sm, dstH + (r + 8) * strB + cc * 2, lod, v10, v11);
        }
}

// ---------------- prologue: transpose + fp16 hi/lo split ----------------
__global__ void tsplit(const float* __restrict__ src, int which, int K, int N) {
    __shared__ float t[32][33];
    __half *dh, *dl;
    if (which == 0) { dh = g_W1h; dl = g_W1l; }
    else if (which == 1) { dh = g_W2h; dl = g_W2l; }
    else { dh = g_W3h; dl = g_W3l; }
    int e = blockIdx.z, k0 = blockIdx.x * 32, n0 = blockIdx.y * 32;
    int tx = threadIdx.x, ty = threadIdx.y;
    const float* s = src + (size_t)e * K * N;
#pragma unroll
    for (int i = 0; i < 32; i += 8)
        t[ty + i][tx] = s[(size_t)(k0 + ty + i) * N + n0 + tx];
    __syncthreads();
#pragma unroll
    for (int i = 0; i < 32; i += 8) {
        float v = t[tx][ty + i];
        __half h = __float2half_rn(v);
        size_t o = (size_t)e * N * K + (size_t)(n0 + ty + i) * K + k0 + tx;
        dh[o] = h;
        dl[o] = __float2half_rn(v - __half2float(h));
    }
}

// ---------------- main fused kernel: 128 threads, 4 warps, 32x32 tiles ----------------
__global__ void __launch_bounds__(128, 1)
moe_main(const float* __restrict__ x, const float* __restrict__ b1,
         const float* __restrict__ b2, const float* __restrict__ b3) {
    extern __shared__ char sm[];
    const int tid = threadIdx.x, wid = tid >> 5, lid = tid & 31;
    const int g = lid >> 2, t = lid & 3;
    const int wR = wid & 1, wC = wid >> 1;          // 2 x 2 warp grid over 64x64
    const int m0 = blockIdx.x * 64, e = blockIdx.y;
    const uint32_t sb = smem_u32(sm);

    // kick off weight prefetch for panels 0,1 first (overlap with X conversion)
    load_panel(sb, SM_BUF + 0 * BUF_SZ, panel_src(e, 0), tid); CP_COMMIT;
    load_panel(sb, SM_BUF + 1 * BUF_SZ, panel_src(e, 1), tid); CP_COMMIT;

    float* b1s = (float*)(sm + SM_B1);
    float* b2s = (float*)(sm + SM_B2);
    float* b3s = (float*)(sm + SM_B3);
    for (int i = tid; i < HID; i += 128) {
        b1s[i] = b1[e * HID + i];
        b2s[i] = b2[e * HID + i];
    }
    if (tid < DOUT) b3s[tid] = b3[e * DOUT + tid];

    // X tile [64 x 128] -> fp16 hi/lo, row stride 136 halves (272 B)
    for (int i = tid; i < 2048; i += 128) {
        int r = i >> 5, j = i & 31;
        float4 f = ((const float4*)(x + ((size_t)(m0 + r) * NE + e) * DIN))[j];
        uint32_t o = (uint32_t)(r * 136 + j * 4) * 2;
        split_st(sm, SM_XH + o, SM_XL - SM_XH, f.x, f.y);
        split_st(sm, SM_XH + o + 4, SM_XL - SM_XH, f.z, f.w);
    }

    // per-lane fragment bases
    const int mrow = wR * 32 + g, ncol = wC * 32 + t * 2;
    const uint32_t aXb  = SM_XH  + (uint32_t)(mrow * 272 + t * 4);
    const uint32_t aH1b = SM_H1H + (uint32_t)(mrow * 1040 + t * 4);
    const uint32_t aH2b = SM_XH  + (uint32_t)(mrow * 144 + t * 4);
    const uint32_t wbLane = (uint32_t)((wC * 32 + g) * 144 + t * 4);

    float acc[32], out[32];
#pragma unroll
    for (int i = 0; i < 32; i++) { acc[i] = 0.f; out[i] = 0.f; }

    // ---- flat 88-panel pipeline: [wait; sync; prefetch P+2; gemm P; epi] ----
    for (int P = 0; P < 88; ++P) {
        CP_WAIT1;
        __syncthreads();
        if (P + 2 < 88)
            load_panel(sb, SM_BUF + ((P + 2) % 3) * BUF_SZ, panel_src(e, P + 2), tid);
        CP_COMMIT;
        uint32_t wb = SM_BUF + (P % 3) * BUF_SZ + wbLane;

        if (P < 16) {
            gemm32(sm, aXb + (P & 1) * 128, SM_XL - SM_XH, 272, wb, acc);
            if (P & 1) {
                int nc = P >> 1;
                epi32(sm, SM_H1H + nc * 128, SM_H1L - SM_H1H, 1040,
                      b1s + nc * 64, acc, mrow, ncol);
#pragma unroll
                for (int i = 0; i < 32; i++) acc[i] = 0.f;
            }
        } else {
            int Q = P - 16, nc = Q / 9, j = Q - nc * 9;
            if (j < 8) {
                gemm32(sm, aH1b + j * 128, SM_H1L - SM_H1H, 1040, wb, acc);
                if (j == 7) {
                    // h2 chunk -> X region (row stride 144 B); read at next panel after sync
                    epi32(sm, SM_XH, SM_XL - SM_XH, 144, b2s + nc * 64, acc, mrow, ncol);
#pragma unroll
                    for (int i = 0; i < 32; i++) acc[i] = 0.f;
                }
            } else {
                gemm32(sm, aH2b, SM_XL - SM_XH, 144, wb, out);
            }
        }
    }

    // ---- write partial [e][m][64] ----
    float* dst = g_part + ((size_t)e * BATCH + m0) * DOUT;
#pragma unroll
    for (int mb = 0; mb < 2; mb++)
#pragma unroll
        for (int nb = 0; nb < 4; nb++) {
            const float* c = out + (mb * 4 + nb) * 4;
            int r = mrow + mb * 16, cc = ncol + nb * 8;
            *(float2*)(dst + (size_t)r * DOUT + cc) =
                make_float2(c[0] + b3s[cc], c[1] + b3s[cc + 1]);
            *(float2*)(dst + (size_t)(r + 8) * DOUT + cc) =
                make_float2(c[2] + b3s[cc], c[3] + b3s[cc + 1]);
        }
}

// ---------------- deterministic expert reduction ----------------
__global__ void reduce_out(float* __restrict__ out) {
    int i = blockIdx.x * blockDim.x + threadIdx.x;
    float s = 0.f;
#pragma unroll
    for (int e = 0; e < NE; e++) s += g_part[(size_t)e * BATCH * DOUT + i];
    out[i] = s;
}

// ---------------- launcher ----------------
extern "C" void kernel_launch(void* const* d_in, const int* in_sizes, int n_in,
                              void* d_out, int out_size) {
    const float* x  = (const float*)d_in[0];
    const float* W1 = (const float*)d_in[1];
    const float* b1 = (const float*)d_in[2];
    const float* W2 = (const float*)d_in[3];
    const float* b2 = (const float*)d_in[4];
    const float* W3 = (const float*)d_in[5];
    const float* b3 = (const float*)d_in[6];
    float* out = (float*)d_out;

    cudaFuncSetAttribute(moe_main, cudaFuncAttributeMaxDynamicSharedMemorySize, SMEM_SZ);

    dim3 t32(32, 8);
    tsplit<<<dim3(DIN / 32, HID / 32, NE), t32>>>(W1, 0, DIN, HID);
    tsplit<<<dim3(HID / 32, HID / 32, NE), t32>>>(W2, 1, HID, HID);
    tsplit<<<dim3(HID / 32, DOUT / 32, NE), t32>>>(W3, 2, HID, DOUT);

    moe_main<<<dim3(BATCH / 64, NE), 128, SMEM_SZ>>>(x, b1, b2, b3);

    reduce_out<<<(BATCH * DOUT) / 256, 256>>>(out);
}